// round 6
// baseline (speedup 1.0000x reference)
#include <cuda_runtime.h>
#include <cuda_fp16.h>
#include <cstdint>

#define B_DIM 4
#define C_DIM 128
#define L_DIM 24
#define HW_DIM 4096

#define NTHREADS 512

// SMEM layout (all swizzled):
//  weights: 256B rows, 128 rows = 32KB each
#define SM_MHI 0
#define SM_MLO 32768
#define SM_WHI 65536
#define SM_WLO 98304
//  per-group B buffers: 128B rows (64 fp16 cols), 128 rows = 16KB each
#define SM_GRP0 131072
#define GRP_STRIDE 49152
#define SMEM_BYTES 229376

__device__ __align__(16) float g_M[C_DIM * C_DIM];             // (U@V)[c][k]
__device__ __align__(16) float g_decay[B_DIM * L_DIM * C_DIM]; // exp(-softplus(lam)*dt)

// ---------------- helpers ----------------
__device__ __forceinline__ uint32_t smem_u32(const void* p) {
    uint32_t a;
    asm("{ .reg .u64 t; cvta.to.shared.u64 t, %1; cvt.u32.u64 %0, t; }" : "=r"(a) : "l"(p));
    return a;
}
// 256B-row swizzle (weights): chunk(16B) index xored with row&7
__device__ __forceinline__ uint32_t woff(int r, int cb) {
    return (uint32_t)(r * 256 + ((((cb >> 4) ^ (r & 7))) << 4) + (cb & 15));
}
// 128B-row swizzle (B buffers)
__device__ __forceinline__ uint32_t boff(int r, int cb) {
    return (uint32_t)(r * 128 + ((((cb >> 4) ^ (r & 7)) & 7) << 4) + (cb & 15));
}
__device__ __forceinline__ void ldsm4(uint32_t& r0, uint32_t& r1, uint32_t& r2, uint32_t& r3, uint32_t a) {
    asm volatile("ldmatrix.sync.aligned.m8n8.x4.shared.b16 {%0,%1,%2,%3}, [%4];"
                 : "=r"(r0), "=r"(r1), "=r"(r2), "=r"(r3) : "r"(a));
}
__device__ __forceinline__ void ldsm4t(uint32_t& r0, uint32_t& r1, uint32_t& r2, uint32_t& r3, uint32_t a) {
    asm volatile("ldmatrix.sync.aligned.m8n8.x4.trans.shared.b16 {%0,%1,%2,%3}, [%4];"
                 : "=r"(r0), "=r"(r1), "=r"(r2), "=r"(r3) : "r"(a));
}
__device__ __forceinline__ void mma16816(float* d, const uint32_t* a, const uint32_t* b) {
    asm volatile("mma.sync.aligned.m16n8k16.row.col.f32.f16.f16.f32 "
                 "{%0,%1,%2,%3}, {%4,%5,%6,%7}, {%8,%9}, {%0,%1,%2,%3};"
                 : "+f"(d[0]), "+f"(d[1]), "+f"(d[2]), "+f"(d[3])
                 : "r"(a[0]), "r"(a[1]), "r"(a[2]), "r"(a[3]), "r"(b[0]), "r"(b[1]));
}
__device__ __forceinline__ void split2h(float x0, float x1, uint32_t& hi, uint32_t& lo) {
    asm("cvt.rn.f16x2.f32 %0, %1, %2;" : "=r"(hi) : "f"(x1), "f"(x0));
    float2 hf = __half22float2(*reinterpret_cast<__half2*>(&hi));
    float r0 = x0 - hf.x;
    float r1 = x1 - hf.y;
    asm("cvt.rn.f16x2.f32 %0, %1, %2;" : "=r"(lo) : "f"(r1), "f"(r0));
}
__device__ __forceinline__ float2 join2h(uint32_t hi, uint32_t lo) {
    float2 a = __half22float2(*reinterpret_cast<__half2*>(&hi));
    float2 b = __half22float2(*reinterpret_cast<__half2*>(&lo));
    return make_float2(a.x + b.x, a.y + b.y);
}
#define BAR_GRP(id) asm volatile("bar.sync %0, %1;" :: "r"(id), "r"(256) : "memory")

// ---------------- precompute ----------------
__global__ void precompute_kernel(const float* __restrict__ lam,
                                  const float* __restrict__ U,
                                  const float* __restrict__ V,
                                  const float* __restrict__ listT) {
    int tid = threadIdx.x;
    if (blockIdx.x < 64) {
        int e = blockIdx.x * 256 + tid;
        int c = e >> 7, k = e & 127;
        float s0 = 0.f, s1 = 0.f;
        #pragma unroll 8
        for (int r = 0; r < 64; r += 2) {
            s0 += U[c * 64 + r] * V[r * C_DIM + k];
            s1 += U[c * 64 + r + 1] * V[(r + 1) * C_DIM + k];
        }
        g_M[e] = s0 + s1;
    } else {
        int idx = (blockIdx.x - 64) * 256 + tid;
        if (idx < B_DIM * L_DIM * C_DIM) {
            int c = idx & 127;
            int t = (idx >> 7) % L_DIM;
            int b = idx / (L_DIM * C_DIM);
            float sp = log1pf(expf(lam[c]));
            g_decay[idx] = expf(-sp * listT[b * L_DIM + t]);
        }
    }
}

// 2-pass fp16-split GEMM, k=128: acc[2][4][4] += (Ahi+Alo)[m0..+32][k] * B[k][n0..+32]
__device__ __forceinline__ void gemm64(uint32_t aHi, uint32_t aLo, uint32_t bB,
                                       int m0, int n0, int lane,
                                       float acc[2][4][4]) {
    const int arow = lane & 15;
    const int aq   = lane >> 4;
    #pragma unroll
    for (int k = 0; k < 128; k += 16) {
        uint32_t ah[2][4], al[2][4];
        #pragma unroll
        for (int mt = 0; mt < 2; ++mt) {
            int r  = m0 + mt * 16 + arow;
            int cb = k * 2 + aq * 16;
            uint32_t w = woff(r, cb);
            ldsm4(ah[mt][0], ah[mt][1], ah[mt][2], ah[mt][3], aHi + w);
            ldsm4(al[mt][0], al[mt][1], al[mt][2], al[mt][3], aLo + w);
        }
        #pragma unroll
        for (int ng = 0; ng < 2; ++ng) {
            int rb  = k + arow;
            int cbb = (n0 + ng * 16) * 2 + aq * 16;
            uint32_t bv[4];
            ldsm4t(bv[0], bv[1], bv[2], bv[3], bB + boff(rb, cbb));
            #pragma unroll
            for (int hh = 0; hh < 2; ++hh) {
                const int nt = ng * 2 + hh;
                #pragma unroll
                for (int mt = 0; mt < 2; ++mt) {
                    mma16816(acc[mt][nt], ah[mt], bv + hh * 2);
                    mma16816(acc[mt][nt], al[mt], bv + hh * 2);
                }
            }
        }
    }
}

// ---------------- main kernel ----------------
__global__ __launch_bounds__(NTHREADS, 1)
void recurrent_kernel(const float* __restrict__ x,
                      const float* __restrict__ h0,
                      const float* __restrict__ Wout,
                      float* __restrict__ out,
                      float* __restrict__ hfin) {
    extern __shared__ char smem[];
    const uint32_t sb = smem_u32(smem);

    const int tid  = threadIdx.x;
    const int lane = tid & 31;
    const int grp  = tid >> 8;            // 0 / 1: independent 64-col pipelines
    const int gtid = tid & 255;
    const int gwid = gtid >> 5;           // 0..7 within group
    const int wm   = gwid & 3;
    const int wn   = gwid >> 2;           // 0..1
    const int m0   = wm * 32;
    const int n0   = wn * 32;
    const int g    = lane >> 2;
    const int tq   = lane & 3;
    const int b    = blockIdx.x >> 5;
    const int sg   = (blockIdx.x & 31) * 128 + grp * 64;   // group spatial base
    const int barid = 1 + grp;
    const size_t rstride = (size_t)L_DIM * HW_DIM;

    const uint32_t bxhi = sb + (uint32_t)(SM_GRP0 + grp * GRP_STRIDE);
    const uint32_t bxlo = bxhi + 16384;
    const uint32_t bhb  = bxhi + 32768;

    // staging coords: 8 chunks, each thread one float4 per 16-row stripe
    const int sr  = gtid >> 4;      // 0..15
    const int sc4 = gtid & 15;      // float4 col within 64

    // ---- stationary weights: fp16-split, swizzled ----
    for (int e = tid; e < C_DIM * C_DIM; e += NTHREADS) {
        int r = e >> 7, k = e & 127;
        uint32_t off = woff(r, k * 2);
        float m = g_M[e];
        __half mh = __float2half_rn(m);
        __half ml = __float2half_rn(m - __half2float(mh));
        *(__half*)(smem + SM_MHI + off) = mh;
        *(__half*)(smem + SM_MLO + off) = ml;
        float w = Wout[e];
        __half wh = __float2half_rn(w);
        __half wl = __float2half_rn(w - __half2float(wh));
        *(__half*)(smem + SM_WHI + off) = wh;
        *(__half*)(smem + SM_WLO + off) = wl;
    }

    // ---- initial hidden state fragments ----
    float h[2][4][4];
    #pragma unroll
    for (int mt = 0; mt < 2; ++mt) {
        #pragma unroll
        for (int nt = 0; nt < 4; ++nt) {
            int c_lo = m0 + mt * 16 + g;
            int s    = sg + n0 + nt * 8 + tq * 2;
            float2 v0 = *(const float2*)&h0[(size_t)(b * C_DIM + c_lo) * HW_DIM + s];
            float2 v1 = *(const float2*)&h0[(size_t)(b * C_DIM + c_lo + 8) * HW_DIM + s];
            h[mt][nt][0] = v0.x; h[mt][nt][1] = v0.y;
            h[mt][nt][2] = v1.x; h[mt][nt][3] = v1.y;
        }
    }

    // ---- prefetch x(0) ----
    float4 xr[8];
    #pragma unroll
    for (int it = 0; it < 8; ++it) {
        int r = it * 16 + sr;
        xr[it] = *(const float4*)(x + ((size_t)(b * C_DIM + r) * L_DIM + 0) * HW_DIM
                                    + sg + sc4 * 4);
    }

    __syncthreads();  // weights visible to both groups

    for (int t = 0; t < L_DIM; ++t) {
        // ---- stage x(t): fp32 -> f16 hi/lo ----
        #pragma unroll
        for (int it = 0; it < 8; ++it) {
            int r = it * 16 + sr;
            float4 v = xr[it];
            uint32_t h0p, l0p, h1p, l1p;
            split2h(v.x, v.y, h0p, l0p);
            split2h(v.z, v.w, h1p, l1p);
            uint32_t off = boff(r, sc4 * 8);
            *(uint2*)(smem + (bxhi - sb) + off) = make_uint2(h0p, h1p);
            *(uint2*)(smem + (bxlo - sb) + off) = make_uint2(l0p, l1p);
        }
        BAR_GRP(barid);

        // decay factors (issue early)
        const float* dk = &g_decay[(b * L_DIM + t) * C_DIM];
        float dA0 = __ldg(&dk[m0 + g]);
        float dB0 = __ldg(&dk[m0 + 8 + g]);
        float dA1 = __ldg(&dk[m0 + 16 + g]);
        float dB1 = __ldg(&dk[m0 + 24 + g]);

        // ---- GEMM1: u = M @ x ----
        float acc[2][4][4];
        #pragma unroll
        for (int mt = 0; mt < 2; ++mt)
            #pragma unroll
            for (int nt = 0; nt < 4; ++nt)
                #pragma unroll
                for (int q = 0; q < 4; ++q) acc[mt][nt][q] = 0.f;
        gemm64(sb + SM_MHI, sb + SM_MLO, bxhi, m0, n0, lane, acc);

        // ---- recurrence ----
        #pragma unroll
        for (int nt = 0; nt < 4; ++nt) {
            h[0][nt][0] = dA0 * h[0][nt][0] + acc[0][nt][0];
            h[0][nt][1] = dA0 * h[0][nt][1] + acc[0][nt][1];
            h[0][nt][2] = dB0 * h[0][nt][2] + acc[0][nt][2];
            h[0][nt][3] = dB0 * h[0][nt][3] + acc[0][nt][3];
            h[1][nt][0] = dA1 * h[1][nt][0] + acc[1][nt][0];
            h[1][nt][1] = dA1 * h[1][nt][1] + acc[1][nt][1];
            h[1][nt][2] = dB1 * h[1][nt][2] + acc[1][nt][2];
            h[1][nt][3] = dB1 * h[1][nt][3] + acc[1][nt][3];
        }

        // ---- residual x from SMEM (hi+lo reconstruction) ----
        #pragma unroll
        for (int mt = 0; mt < 2; ++mt) {
            #pragma unroll
            for (int nt = 0; nt < 4; ++nt) {
                int c_lo = m0 + mt * 16 + g;
                int cb   = (n0 + nt * 8 + tq * 2) * 2;
                uint32_t o0 = boff(c_lo, cb);
                uint32_t o1 = boff(c_lo + 8, cb);
                uint32_t xh0 = *(const uint32_t*)(smem + (bxhi - sb) + o0);
                uint32_t xl0 = *(const uint32_t*)(smem + (bxlo - sb) + o0);
                uint32_t xh1 = *(const uint32_t*)(smem + (bxhi - sb) + o1);
                uint32_t xl1 = *(const uint32_t*)(smem + (bxlo - sb) + o1);
                float2 r0 = join2h(xh0, xl0);
                float2 r1 = join2h(xh1, xl1);
                acc[mt][nt][0] = r0.x; acc[mt][nt][1] = r0.y;
                acc[mt][nt][2] = r1.x; acc[mt][nt][3] = r1.y;
            }
        }
        BAR_GRP(barid);   // all group warps done reading BX / finished GEMM1

        // ---- write h (f16 hi) into BH ----
        #pragma unroll
        for (int mt = 0; mt < 2; ++mt) {
            #pragma unroll
            for (int nt = 0; nt < 4; ++nt) {
                int c_lo = m0 + mt * 16 + g;
                int cb   = (n0 + nt * 8 + tq * 2) * 2;
                uint32_t hi0, lo0, hi1, lo1;
                split2h(h[mt][nt][0], h[mt][nt][1], hi0, lo0);
                split2h(h[mt][nt][2], h[mt][nt][3], hi1, lo1);
                (void)lo0; (void)lo1;
                *(uint32_t*)(smem + (bhb - sb) + boff(c_lo, cb))     = hi0;
                *(uint32_t*)(smem + (bhb - sb) + boff(c_lo + 8, cb)) = hi1;
            }
        }

        // ---- prefetch x(t+1) (overlaps barrier + GEMM2) ----
        {
            int tn = (t + 1 < L_DIM) ? t + 1 : t;
            #pragma unroll
            for (int it = 0; it < 8; ++it) {
                int r = it * 16 + sr;
                xr[it] = *(const float4*)(x + ((size_t)(b * C_DIM + r) * L_DIM + tn) * HW_DIM
                                            + sg + sc4 * 4);
            }
        }
        BAR_GRP(barid);   // BH visible

        // ---- GEMM2: out = x + Wout @ h ----
        gemm64(sb + SM_WHI, sb + SM_WLO, bhb, m0, n0, lane, acc);

        // ---- store output ----
        #pragma unroll
        for (int mt = 0; mt < 2; ++mt) {
            #pragma unroll
            for (int nt = 0; nt < 4; ++nt) {
                int d_lo = m0 + mt * 16 + g;
                float* po = out + ((size_t)(b * C_DIM + d_lo) * L_DIM + t) * HW_DIM
                                + sg + n0 + nt * 8 + tq * 2;
                *(float2*)po = make_float2(acc[mt][nt][0], acc[mt][nt][1]);
                *(float2*)(po + 8 * rstride) = make_float2(acc[mt][nt][2], acc[mt][nt][3]);
            }
        }
        // no extra barrier: next iteration's staging writes BX, whose readers
        // (GEMM1/residual of THIS t) all arrived at the post-residual barrier.
    }

    // ---- final hidden state ----
    #pragma unroll
    for (int mt = 0; mt < 2; ++mt) {
        #pragma unroll
        for (int nt = 0; nt < 4; ++nt) {
            int c_lo = m0 + mt * 16 + g;
            int s    = sg + n0 + nt * 8 + tq * 2;
            *(float2*)&hfin[(size_t)(b * C_DIM + c_lo) * HW_DIM + s] =
                make_float2(h[mt][nt][0], h[mt][nt][1]);
            *(float2*)&hfin[(size_t)(b * C_DIM + c_lo + 8) * HW_DIM + s] =
                make_float2(h[mt][nt][2], h[mt][nt][3]);
        }
    }
}

extern "C" void kernel_launch(void* const* d_in, const int* in_sizes, int n_in,
                              void* d_out, int out_size) {
    const float* x     = (const float*)d_in[0];
    const float* h0    = (const float*)d_in[1];
    const float* listT = (const float*)d_in[2];
    const float* lam   = (const float*)d_in[3];
    const float* U     = (const float*)d_in[4];
    const float* V     = (const float*)d_in[5];
    const float* Wout  = (const float*)d_in[6];

    float* out  = (float*)d_out;
    float* hfin = out + (size_t)B_DIM * C_DIM * L_DIM * HW_DIM;

    precompute_kernel<<<112, 256>>>(lam, U, V, listT);

    cudaFuncSetAttribute(recurrent_kernel,
                         cudaFuncAttributeMaxDynamicSharedMemorySize, SMEM_BYTES);
    recurrent_kernel<<<B_DIM * (HW_DIM / 128), NTHREADS, SMEM_BYTES>>>(x, h0, Wout, out, hfin);
}

// round 7
// speedup vs baseline: 1.3381x; 1.3381x over previous
#include <cuda_runtime.h>
#include <cuda_fp16.h>
#include <cstdint>

#define B_DIM 4
#define C_DIM 128
#define L_DIM 24
#define HW_DIM 4096

#define SK   136          // fp16 row stride in elements
#define ROWB (SK * 2)     // 272 bytes/row

#define SM_MHI 0
#define SM_WHI 34816
#define SM_BHI 69632
#define SM_BLO 104448
#define SMEM_BYTES 139264

#define NTHREADS 512

__device__ __align__(16) float g_M[C_DIM * C_DIM];             // (U@V)[c][k]
__device__ __align__(16) float g_decay[B_DIM * L_DIM * C_DIM]; // exp(-softplus(lam)*dt)

// ---------------- helpers ----------------
__device__ __forceinline__ uint32_t smem_u32(const void* p) {
    uint32_t a;
    asm("{ .reg .u64 t; cvta.to.shared.u64 t, %1; cvt.u32.u64 %0, t; }" : "=r"(a) : "l"(p));
    return a;
}
__device__ __forceinline__ void ldsm4(uint32_t& r0, uint32_t& r1, uint32_t& r2, uint32_t& r3, uint32_t a) {
    asm volatile("ldmatrix.sync.aligned.m8n8.x4.shared.b16 {%0,%1,%2,%3}, [%4];"
                 : "=r"(r0), "=r"(r1), "=r"(r2), "=r"(r3) : "r"(a));
}
__device__ __forceinline__ void ldsm4t(uint32_t& r0, uint32_t& r1, uint32_t& r2, uint32_t& r3, uint32_t a) {
    asm volatile("ldmatrix.sync.aligned.m8n8.x4.trans.shared.b16 {%0,%1,%2,%3}, [%4];"
                 : "=r"(r0), "=r"(r1), "=r"(r2), "=r"(r3) : "r"(a));
}
__device__ __forceinline__ void mma16816(float* d, const uint32_t* a, const uint32_t* b) {
    asm volatile("mma.sync.aligned.m16n8k16.row.col.f32.f16.f16.f32 "
                 "{%0,%1,%2,%3}, {%4,%5,%6,%7}, {%8,%9}, {%0,%1,%2,%3};"
                 : "+f"(d[0]), "+f"(d[1]), "+f"(d[2]), "+f"(d[3])
                 : "r"(a[0]), "r"(a[1]), "r"(a[2]), "r"(a[3]), "r"(b[0]), "r"(b[1]));
}
__device__ __forceinline__ void split2h(float x0, float x1, uint32_t& hi, uint32_t& lo) {
    asm("cvt.rn.f16x2.f32 %0, %1, %2;" : "=r"(hi) : "f"(x1), "f"(x0));
    float2 hf = __half22float2(*reinterpret_cast<__half2*>(&hi));
    float r0 = x0 - hf.x;
    float r1 = x1 - hf.y;
    asm("cvt.rn.f16x2.f32 %0, %1, %2;" : "=r"(lo) : "f"(r1), "f"(r0));
}
__device__ __forceinline__ float2 join2h(uint32_t hi, uint32_t lo) {
    float2 a = __half22float2(*reinterpret_cast<__half2*>(&hi));
    float2 b = __half22float2(*reinterpret_cast<__half2*>(&lo));
    return make_float2(a.x + b.x, a.y + b.y);
}

// ---------------- precompute ----------------
__global__ void precompute_kernel(const float* __restrict__ lam,
                                  const float* __restrict__ U,
                                  const float* __restrict__ V,
                                  const float* __restrict__ listT) {
    int tid = threadIdx.x;
    if (blockIdx.x < 64) {
        int e = blockIdx.x * 256 + tid;
        int c = e >> 7, k = e & 127;
        float s0 = 0.f, s1 = 0.f;
        #pragma unroll 8
        for (int r = 0; r < 64; r += 2) {
            s0 += U[c * 64 + r] * V[r * C_DIM + k];
            s1 += U[c * 64 + r + 1] * V[(r + 1) * C_DIM + k];
        }
        g_M[e] = s0 + s1;
    } else {
        int idx = (blockIdx.x - 64) * 256 + tid;
        if (idx < B_DIM * L_DIM * C_DIM) {
            int c = idx & 127;
            int t = (idx >> 7) % L_DIM;
            int b = idx / (L_DIM * C_DIM);
            float sp = log1pf(expf(lam[c]));
            g_decay[idx] = expf(-sp * listT[b * L_DIM + t]);
        }
    }
}

// single-pass fp16 GEMM, k=128: acc[2][4][4] += A[m0..+32][k] * B[k][n0..+32]
__device__ __forceinline__ void gemm128(uint32_t aB, uint32_t bB,
                                        int m0, int n0, int lane,
                                        float acc[2][4][4]) {
    const int arow = lane & 15;
    const int aq   = lane >> 4;
    #pragma unroll
    for (int k = 0; k < 128; k += 16) {
        uint32_t ah[2][4];
        #pragma unroll
        for (int mt = 0; mt < 2; ++mt) {
            uint32_t addr = aB + (uint32_t)((m0 + mt * 16 + arow) * ROWB + k * 2 + aq * 16);
            ldsm4(ah[mt][0], ah[mt][1], ah[mt][2], ah[mt][3], addr);
        }
        #pragma unroll
        for (int ng = 0; ng < 2; ++ng) {
            uint32_t addr = bB + (uint32_t)((k + arow) * ROWB + (n0 + ng * 16) * 2 + aq * 16);
            uint32_t bv[4];
            ldsm4t(bv[0], bv[1], bv[2], bv[3], addr);
            #pragma unroll
            for (int hh = 0; hh < 2; ++hh) {
                const int nt = ng * 2 + hh;
                #pragma unroll
                for (int mt = 0; mt < 2; ++mt)
                    mma16816(acc[mt][nt], ah[mt], bv + hh * 2);
            }
        }
    }
}

// ---------------- main kernel ----------------
__global__ __launch_bounds__(NTHREADS, 1)
void recurrent_kernel(const float* __restrict__ x,
                      const float* __restrict__ h0,
                      const float* __restrict__ Wout,
                      float* __restrict__ out,
                      float* __restrict__ hfin) {
    extern __shared__ char smem[];
    const uint32_t sb = smem_u32(smem);

    const int tid  = threadIdx.x;
    const int lane = tid & 31;
    const int wid  = tid >> 5;            // 0..15
    const int b    = blockIdx.x >> 5;
    const int s0   = (blockIdx.x & 31) * 128;
    const int wm   = wid & 3;
    const int wn   = wid >> 2;
    const int m0   = wm * 32;
    const int n0   = wn * 32;
    const int g    = lane >> 2;
    const int tq   = lane & 3;
    const size_t rstride = (size_t)L_DIM * HW_DIM;

    const int sr  = tid >> 5;       // staging base row
    const int sc4 = tid & 31;       // staging float4 column

    // ---- stationary weights (fp16 hi only) ----
    for (int e = tid; e < C_DIM * C_DIM; e += NTHREADS) {
        int r = e >> 7, k = e & 127;
        uint32_t off = (uint32_t)(r * ROWB + k * 2);
        *(__half*)(smem + SM_MHI + off) = __float2half_rn(g_M[e]);
        *(__half*)(smem + SM_WHI + off) = __float2half_rn(Wout[e]);
    }

    // ---- initial hidden state fragments ----
    float h[2][4][4];
    #pragma unroll
    for (int mt = 0; mt < 2; ++mt) {
        #pragma unroll
        for (int nt = 0; nt < 4; ++nt) {
            int c_lo = m0 + mt * 16 + g;
            int s    = s0 + n0 + nt * 8 + tq * 2;
            float2 v0 = *(const float2*)&h0[(size_t)(b * C_DIM + c_lo) * HW_DIM + s];
            float2 v1 = *(const float2*)&h0[(size_t)(b * C_DIM + c_lo + 8) * HW_DIM + s];
            h[mt][nt][0] = v0.x; h[mt][nt][1] = v0.y;
            h[mt][nt][2] = v1.x; h[mt][nt][3] = v1.y;
        }
    }

    // ---- prefetch x(0) ----
    float4 xr[8];
    #pragma unroll
    for (int it = 0; it < 8; ++it) {
        int r = it * 16 + sr;
        xr[it] = *(const float4*)(x + ((size_t)(b * C_DIM + r) * L_DIM + 0) * HW_DIM
                                    + s0 + sc4 * 4);
    }

    __syncthreads();  // weights ready

    for (int t = 0; t < L_DIM; ++t) {
        // ---- stage x(t): fp32 -> f16 hi/lo ----
        #pragma unroll
        for (int it = 0; it < 8; ++it) {
            int r = it * 16 + sr;
            float4 v = xr[it];
            uint32_t h0p, l0p, h1p, l1p;
            split2h(v.x, v.y, h0p, l0p);
            split2h(v.z, v.w, h1p, l1p);
            uint32_t off = (uint32_t)(r * ROWB + sc4 * 8);
            *(uint2*)(smem + SM_BHI + off) = make_uint2(h0p, h1p);
            *(uint2*)(smem + SM_BLO + off) = make_uint2(l0p, l1p);
        }
        __syncthreads();

        // ---- GEMM1: u = M @ x ----
        float acc[2][4][4];
        #pragma unroll
        for (int mt = 0; mt < 2; ++mt)
            #pragma unroll
            for (int nt = 0; nt < 4; ++nt)
                #pragma unroll
                for (int q = 0; q < 4; ++q) acc[mt][nt][q] = 0.f;
        gemm128(sb + SM_MHI, sb + SM_BHI, m0, n0, lane, acc);

        // ---- recurrence: h = decay(c)*h + u ----
        {
            const float* dk = &g_decay[(b * L_DIM + t) * C_DIM];
            #pragma unroll
            for (int mt = 0; mt < 2; ++mt) {
                float dA = __ldg(&dk[m0 + mt * 16 + g]);
                float dB = __ldg(&dk[m0 + mt * 16 + 8 + g]);
                #pragma unroll
                for (int nt = 0; nt < 4; ++nt) {
                    h[mt][nt][0] = dA * h[mt][nt][0] + acc[mt][nt][0];
                    h[mt][nt][1] = dA * h[mt][nt][1] + acc[mt][nt][1];
                    h[mt][nt][2] = dB * h[mt][nt][2] + acc[mt][nt][2];
                    h[mt][nt][3] = dB * h[mt][nt][3] + acc[mt][nt][3];
                }
            }
        }

        // ---- residual x from SMEM (hi+lo fp16 reconstruction) ----
        #pragma unroll
        for (int mt = 0; mt < 2; ++mt) {
            #pragma unroll
            for (int nt = 0; nt < 4; ++nt) {
                int c_lo = m0 + mt * 16 + g;
                uint32_t off0 = (uint32_t)(c_lo * ROWB + (n0 + nt * 8 + tq * 2) * 2);
                uint32_t off1 = off0 + 8 * ROWB;
                uint32_t xh0 = *(const uint32_t*)(smem + SM_BHI + off0);
                uint32_t xl0 = *(const uint32_t*)(smem + SM_BLO + off0);
                uint32_t xh1 = *(const uint32_t*)(smem + SM_BHI + off1);
                uint32_t xl1 = *(const uint32_t*)(smem + SM_BLO + off1);
                float2 r0 = join2h(xh0, xl0);
                float2 r1 = join2h(xh1, xl1);
                acc[mt][nt][0] = r0.x; acc[mt][nt][1] = r0.y;
                acc[mt][nt][2] = r1.x; acc[mt][nt][3] = r1.y;
            }
        }

        __syncthreads();   // all warps done reading x tile

        // ---- write h (f16 hi) into B buffer for GEMM2 ----
        #pragma unroll
        for (int mt = 0; mt < 2; ++mt) {
            #pragma unroll
            for (int nt = 0; nt < 4; ++nt) {
                int c_lo = m0 + mt * 16 + g;
                int scol = n0 + nt * 8 + tq * 2;
                uint32_t hi0, lo0, hi1, lo1;
                split2h(h[mt][nt][0], h[mt][nt][1], hi0, lo0);
                split2h(h[mt][nt][2], h[mt][nt][3], hi1, lo1);
                (void)lo0; (void)lo1;
                uint32_t off0 = (uint32_t)(c_lo * ROWB + scol * 2);
                uint32_t off1 = off0 + 8 * ROWB;
                *(uint32_t*)(smem + SM_BHI + off0) = hi0;
                *(uint32_t*)(smem + SM_BHI + off1) = hi1;
            }
        }

        // ---- prefetch x(t+1) (hidden behind GEMM2) ----
        {
            int tn = (t + 1 < L_DIM) ? t + 1 : t;
            #pragma unroll
            for (int it = 0; it < 8; ++it) {
                int r = it * 16 + sr;
                xr[it] = *(const float4*)(x + ((size_t)(b * C_DIM + r) * L_DIM + tn) * HW_DIM
                                            + s0 + sc4 * 4);
            }
        }
        __syncthreads();

        // ---- GEMM2: out = x + Wout @ h ----
        gemm128(sb + SM_WHI, sb + SM_BHI, m0, n0, lane, acc);

        // ---- store output ----
        #pragma unroll
        for (int mt = 0; mt < 2; ++mt) {
            #pragma unroll
            for (int nt = 0; nt < 4; ++nt) {
                int d_lo = m0 + mt * 16 + g;
                float* po = out + ((size_t)(b * C_DIM + d_lo) * L_DIM + t) * HW_DIM
                                + s0 + n0 + nt * 8 + tq * 2;
                *(float2*)po = make_float2(acc[mt][nt][0], acc[mt][nt][1]);
                *(float2*)(po + 8 * rstride) = make_float2(acc[mt][nt][2], acc[mt][nt][3]);
            }
        }
        __syncthreads();   // GEMM2 reads of B done before next staging overwrites
    }

    // ---- final hidden state ----
    #pragma unroll
    for (int mt = 0; mt < 2; ++mt) {
        #pragma unroll
        for (int nt = 0; nt < 4; ++nt) {
            int c_lo = m0 + mt * 16 + g;
            int s    = s0 + n0 + nt * 8 + tq * 2;
            *(float2*)&hfin[(size_t)(b * C_DIM + c_lo) * HW_DIM + s] =
                make_float2(h[mt][nt][0], h[mt][nt][1]);
            *(float2*)&hfin[(size_t)(b * C_DIM + c_lo + 8) * HW_DIM + s] =
                make_float2(h[mt][nt][2], h[mt][nt][3]);
        }
    }
}

extern "C" void kernel_launch(void* const* d_in, const int* in_sizes, int n_in,
                              void* d_out, int out_size) {
    const float* x     = (const float*)d_in[0];
    const float* h0    = (const float*)d_in[1];
    const float* listT = (const float*)d_in[2];
    const float* lam   = (const float*)d_in[3];
    const float* U     = (const float*)d_in[4];
    const float* V     = (const float*)d_in[5];
    const float* Wout  = (const float*)d_in[6];

    float* out  = (float*)d_out;
    float* hfin = out + (size_t)B_DIM * C_DIM * L_DIM * HW_DIM;

    precompute_kernel<<<112, 256>>>(lam, U, V, listT);

    cudaFuncSetAttribute(recurrent_kernel,
                         cudaFuncAttributeMaxDynamicSharedMemorySize, SMEM_BYTES);
    recurrent_kernel<<<B_DIM * (HW_DIM / 128), NTHREADS, SMEM_BYTES>>>(x, h0, Wout, out, hfin);
}